// round 4
// baseline (speedup 1.0000x reference)
#include <cuda_runtime.h>

#define NN 100000
#define EE 3200000
#define E4 (EE / 4)

// Scratch (__device__ globals; no allocation allowed)
__device__ float  g_deg[NN];
__device__ float  g_dinv[NN];
__device__ float2 g_ab[NN];    // (dinv*x0, dinv*x1) per node
__device__ float2 g_sab[NN];   // layer-1 accumulators
__device__ float  g_q[NN];
__device__ float  g_t[NN];

__device__ __forceinline__ void red_add_v2(float2* addr, float a, float b) {
    asm volatile("red.global.add.v2.f32 [%0], {%1, %2};"
                 :: "l"(addr), "f"(a), "f"(b) : "memory");
}
__device__ __forceinline__ void red_add_f(float* addr, float v) {
    asm volatile("red.global.add.f32 [%0], %1;"
                 :: "l"(addr), "f"(v) : "memory");
}

// K-deg: degree count (col only). 4 int4 per thread, loads batched.
__global__ void __launch_bounds__(256) k_deg(const int4* __restrict__ col4) {
    int base = (blockIdx.x * blockDim.x + threadIdx.x) * 4;
    if (base + 3 < E4) {
        int4 c0 = __ldg(&col4[base + 0]);
        int4 c1 = __ldg(&col4[base + 1]);
        int4 c2 = __ldg(&col4[base + 2]);
        int4 c3 = __ldg(&col4[base + 3]);
        red_add_f(&g_deg[c0.x], 1.0f); red_add_f(&g_deg[c0.y], 1.0f);
        red_add_f(&g_deg[c0.z], 1.0f); red_add_f(&g_deg[c0.w], 1.0f);
        red_add_f(&g_deg[c1.x], 1.0f); red_add_f(&g_deg[c1.y], 1.0f);
        red_add_f(&g_deg[c1.z], 1.0f); red_add_f(&g_deg[c1.w], 1.0f);
        red_add_f(&g_deg[c2.x], 1.0f); red_add_f(&g_deg[c2.y], 1.0f);
        red_add_f(&g_deg[c2.z], 1.0f); red_add_f(&g_deg[c2.w], 1.0f);
        red_add_f(&g_deg[c3.x], 1.0f); red_add_f(&g_deg[c3.y], 1.0f);
        red_add_f(&g_deg[c3.z], 1.0f); red_add_f(&g_deg[c3.w], 1.0f);
    } else {
        for (int u = 0; u < 4; u++) {
            int idx = base + u;
            if (idx < E4) {
                int4 c = __ldg(&col4[idx]);
                red_add_f(&g_deg[c.x], 1.0f); red_add_f(&g_deg[c.y], 1.0f);
                red_add_f(&g_deg[c.z], 1.0f); red_add_f(&g_deg[c.w], 1.0f);
            }
        }
    }
}

// K-node1: dinv = rsqrt(deg + 1 self-loop); (a,b) = dinv * x
__global__ void __launch_bounds__(256) k_node1(const float* __restrict__ x, int n) {
    int i = blockIdx.x * blockDim.x + threadIdx.x;
    if (i < n) {
        float dinv = rsqrtf(g_deg[i] + 1.0f);
        float2 xi = ((const float2*)x)[i];
        g_dinv[i] = dinv;
        g_ab[i] = make_float2(dinv * xi.x, dinv * xi.y);
    }
}

// K-scatter1: 16 edges per thread; gather then vector-RED.
__global__ void __launch_bounds__(256) k_scatter1(const int4* __restrict__ row4,
                                                  const int4* __restrict__ col4) {
    int base = (blockIdx.x * blockDim.x + threadIdx.x) * 4;
    if (base + 3 < E4) {
        int4 r0 = __ldg(&row4[base + 0]);
        int4 r1 = __ldg(&row4[base + 1]);
        int4 r2 = __ldg(&row4[base + 2]);
        int4 r3 = __ldg(&row4[base + 3]);
        int4 c0 = __ldg(&col4[base + 0]);
        int4 c1 = __ldg(&col4[base + 1]);
        int4 c2 = __ldg(&col4[base + 2]);
        int4 c3 = __ldg(&col4[base + 3]);
        float2 v00 = __ldg(&g_ab[r0.x]), v01 = __ldg(&g_ab[r0.y]),
               v02 = __ldg(&g_ab[r0.z]), v03 = __ldg(&g_ab[r0.w]);
        float2 v10 = __ldg(&g_ab[r1.x]), v11 = __ldg(&g_ab[r1.y]),
               v12 = __ldg(&g_ab[r1.z]), v13 = __ldg(&g_ab[r1.w]);
        float2 v20 = __ldg(&g_ab[r2.x]), v21 = __ldg(&g_ab[r2.y]),
               v22 = __ldg(&g_ab[r2.z]), v23 = __ldg(&g_ab[r2.w]);
        float2 v30 = __ldg(&g_ab[r3.x]), v31 = __ldg(&g_ab[r3.y]),
               v32 = __ldg(&g_ab[r3.z]), v33 = __ldg(&g_ab[r3.w]);
        red_add_v2(&g_sab[c0.x], v00.x, v00.y); red_add_v2(&g_sab[c0.y], v01.x, v01.y);
        red_add_v2(&g_sab[c0.z], v02.x, v02.y); red_add_v2(&g_sab[c0.w], v03.x, v03.y);
        red_add_v2(&g_sab[c1.x], v10.x, v10.y); red_add_v2(&g_sab[c1.y], v11.x, v11.y);
        red_add_v2(&g_sab[c1.z], v12.x, v12.y); red_add_v2(&g_sab[c1.w], v13.x, v13.y);
        red_add_v2(&g_sab[c2.x], v20.x, v20.y); red_add_v2(&g_sab[c2.y], v21.x, v21.y);
        red_add_v2(&g_sab[c2.z], v22.x, v22.y); red_add_v2(&g_sab[c2.w], v23.x, v23.y);
        red_add_v2(&g_sab[c3.x], v30.x, v30.y); red_add_v2(&g_sab[c3.y], v31.x, v31.y);
        red_add_v2(&g_sab[c3.z], v32.x, v32.y); red_add_v2(&g_sab[c3.w], v33.x, v33.y);
    } else {
        for (int u = 0; u < 4; u++) {
            int idx = base + u;
            if (idx < E4) {
                int4 r = __ldg(&row4[idx]);
                int4 c = __ldg(&col4[idx]);
                float2 v0 = __ldg(&g_ab[r.x]); float2 v1 = __ldg(&g_ab[r.y]);
                float2 v2 = __ldg(&g_ab[r.z]); float2 v3 = __ldg(&g_ab[r.w]);
                red_add_v2(&g_sab[c.x], v0.x, v0.y);
                red_add_v2(&g_sab[c.y], v1.x, v1.y);
                red_add_v2(&g_sab[c.z], v2.x, v2.y);
                red_add_v2(&g_sab[c.w], v3.x, v3.y);
            }
        }
    }
}

// K-node2: reconstruct h1 (64-wide), relu, dot W2 -> q = dinv * p
__global__ void __launch_bounds__(256) k_node2(const float* __restrict__ W1,
                                               const float* __restrict__ b1,
                                               const float* __restrict__ W2, int n) {
    __shared__ float sW10[64], sW11[64], sB1[64], sW2[64];
    int t = threadIdx.x;
    if (t < 64) {
        sW10[t] = W1[t];
        sW11[t] = W1[64 + t];
        sB1[t]  = b1[t];
        sW2[t]  = W2[t];
    }
    __syncthreads();
    int i = blockIdx.x * blockDim.x + t;
    if (i < n) {
        float dinv = g_dinv[i];
        float2 self = g_ab[i];
        float2 acc  = g_sab[i];
        float ca = acc.x + self.x;
        float cb = acc.y + self.y;
        float p = 0.0f;
        #pragma unroll
        for (int j = 0; j < 64; j++) {
            float h = fmaf(dinv, fmaf(ca, sW10[j], cb * sW11[j]), sB1[j]);
            h = fmaxf(h, 0.0f);
            p = fmaf(h, sW2[j], p);
        }
        g_q[i] = dinv * p;
    }
}

// K-scatter2: 16 edges per thread; scalar gather + scalar RED.
__global__ void __launch_bounds__(256) k_scatter2(const int4* __restrict__ row4,
                                                  const int4* __restrict__ col4) {
    int base = (blockIdx.x * blockDim.x + threadIdx.x) * 4;
    if (base + 3 < E4) {
        int4 r0 = __ldg(&row4[base + 0]);
        int4 r1 = __ldg(&row4[base + 1]);
        int4 r2 = __ldg(&row4[base + 2]);
        int4 r3 = __ldg(&row4[base + 3]);
        int4 c0 = __ldg(&col4[base + 0]);
        int4 c1 = __ldg(&col4[base + 1]);
        int4 c2 = __ldg(&col4[base + 2]);
        int4 c3 = __ldg(&col4[base + 3]);
        float q00 = __ldg(&g_q[r0.x]), q01 = __ldg(&g_q[r0.y]),
              q02 = __ldg(&g_q[r0.z]), q03 = __ldg(&g_q[r0.w]);
        float q10 = __ldg(&g_q[r1.x]), q11 = __ldg(&g_q[r1.y]),
              q12 = __ldg(&g_q[r1.z]), q13 = __ldg(&g_q[r1.w]);
        float q20 = __ldg(&g_q[r2.x]), q21 = __ldg(&g_q[r2.y]),
              q22 = __ldg(&g_q[r2.z]), q23 = __ldg(&g_q[r2.w]);
        float q30 = __ldg(&g_q[r3.x]), q31 = __ldg(&g_q[r3.y]),
              q32 = __ldg(&g_q[r3.z]), q33 = __ldg(&g_q[r3.w]);
        red_add_f(&g_t[c0.x], q00); red_add_f(&g_t[c0.y], q01);
        red_add_f(&g_t[c0.z], q02); red_add_f(&g_t[c0.w], q03);
        red_add_f(&g_t[c1.x], q10); red_add_f(&g_t[c1.y], q11);
        red_add_f(&g_t[c1.z], q12); red_add_f(&g_t[c1.w], q13);
        red_add_f(&g_t[c2.x], q20); red_add_f(&g_t[c2.y], q21);
        red_add_f(&g_t[c2.z], q22); red_add_f(&g_t[c2.w], q23);
        red_add_f(&g_t[c3.x], q30); red_add_f(&g_t[c3.y], q31);
        red_add_f(&g_t[c3.z], q32); red_add_f(&g_t[c3.w], q33);
    } else {
        for (int u = 0; u < 4; u++) {
            int idx = base + u;
            if (idx < E4) {
                int4 r = __ldg(&row4[idx]);
                int4 c = __ldg(&col4[idx]);
                red_add_f(&g_t[c.x], __ldg(&g_q[r.x]));
                red_add_f(&g_t[c.y], __ldg(&g_q[r.y]));
                red_add_f(&g_t[c.z], __ldg(&g_q[r.z]));
                red_add_f(&g_t[c.w], __ldg(&g_q[r.w]));
            }
        }
    }
}

// K-final
__global__ void __launch_bounds__(256) k_final(const float* __restrict__ b2,
                                               float* __restrict__ out, int n) {
    int i = blockIdx.x * blockDim.x + threadIdx.x;
    if (i < n) {
        out[i] = fmaf(g_dinv[i], g_t[i] + g_q[i], b2[0]);
    }
}

extern "C" void kernel_launch(void* const* d_in, const int* in_sizes, int n_in,
                              void* d_out, int out_size) {
    const float* x   = (const float*)d_in[0];
    const int*   ei  = (const int*)d_in[1];
    const float* W1  = (const float*)d_in[2];
    const float* b1  = (const float*)d_in[3];
    const float* W2  = (const float*)d_in[4];
    const float* b2  = (const float*)d_in[5];
    float* out = (float*)d_out;

    const int n = NN;
    const int4* row4 = (const int4*)ei;
    const int4* col4 = (const int4*)(ei + EE);

    const int TB = 256;
    const int gN = (n + TB - 1) / TB;
    const int gE = (E4 / 4 + TB - 1) / TB;   // 4 int4 (16 edges) per thread

    // Zero accumulators via HW memset (graph-capturable, async on stream 0)
    static float* p_deg = nullptr;
    static float2* p_sab = nullptr;
    static float* p_t = nullptr;
    if (!p_deg) {
        cudaGetSymbolAddress((void**)&p_deg, g_deg);
        cudaGetSymbolAddress((void**)&p_sab, g_sab);
        cudaGetSymbolAddress((void**)&p_t, g_t);
    }
    cudaMemsetAsync(p_deg, 0, NN * sizeof(float));
    cudaMemsetAsync(p_sab, 0, NN * sizeof(float2));
    cudaMemsetAsync(p_t, 0, NN * sizeof(float));

    k_deg     <<<gE, TB>>>(col4);
    k_node1   <<<gN, TB>>>(x, n);
    k_scatter1<<<gE, TB>>>(row4, col4);
    k_node2   <<<gN, TB>>>(W1, b1, W2, n);
    k_scatter2<<<gE, TB>>>(row4, col4);
    k_final   <<<gN, TB>>>(b2, out, n);
}

// round 5
// speedup vs baseline: 1.1294x; 1.1294x over previous
#include <cuda_runtime.h>

#define NN 100000
#define EE 3200000
#define E4 (EE / 4)

// Scratch (__device__ globals; no allocation allowed)
__device__ float  g_deg[NN];
__device__ float  g_dinv[NN];
__device__ float2 g_ab[NN];    // (dinv*x0, dinv*x1) per node
__device__ float2 g_sab[NN];   // layer-1 accumulators
__device__ float  g_q[NN];
__device__ float  g_t[NN];

__device__ __forceinline__ void red_add_v2(float2* addr, float a, float b) {
    asm volatile("red.global.add.v2.f32 [%0], {%1, %2};"
                 :: "l"(addr), "f"(a), "f"(b) : "memory");
}
__device__ __forceinline__ void red_add_f(float* addr, float v) {
    asm volatile("red.global.add.f32 [%0], %1;"
                 :: "l"(addr), "f"(v) : "memory");
}

// K-deg: degree count (col only). 2 int4 per thread, groups kept sequential
// (low MLP_p1 — avoids cross-CTA L1tex queue contention).
__global__ void __launch_bounds__(256) k_deg(const int4* __restrict__ col4) {
    int i = (blockIdx.x * blockDim.x + threadIdx.x) * 2;
    #pragma unroll
    for (int u = 0; u < 2; u++) {
        int idx = i + u;
        if (idx < E4) {
            int4 c = __ldg(&col4[idx]);
            red_add_f(&g_deg[c.x], 1.0f);
            red_add_f(&g_deg[c.y], 1.0f);
            red_add_f(&g_deg[c.z], 1.0f);
            red_add_f(&g_deg[c.w], 1.0f);
        }
    }
}

// K-node1: dinv = rsqrt(deg + 1 self-loop); (a,b) = dinv * x
__global__ void __launch_bounds__(256) k_node1(const float* __restrict__ x, int n) {
    int i = blockIdx.x * blockDim.x + threadIdx.x;
    if (i < n) {
        float dinv = rsqrtf(g_deg[i] + 1.0f);
        float2 xi = ((const float2*)x)[i];
        g_dinv[i] = dinv;
        g_ab[i] = make_float2(dinv * xi.x, dinv * xi.y);
    }
}

// K-scatter1: 8 edges per thread in two sequential int4 groups.
__global__ void __launch_bounds__(256) k_scatter1(const int4* __restrict__ row4,
                                                  const int4* __restrict__ col4) {
    int i = (blockIdx.x * blockDim.x + threadIdx.x) * 2;
    #pragma unroll
    for (int u = 0; u < 2; u++) {
        int idx = i + u;
        if (idx < E4) {
            int4 r = __ldg(&row4[idx]);
            int4 c = __ldg(&col4[idx]);
            float2 v0 = __ldg(&g_ab[r.x]);
            float2 v1 = __ldg(&g_ab[r.y]);
            float2 v2 = __ldg(&g_ab[r.z]);
            float2 v3 = __ldg(&g_ab[r.w]);
            red_add_v2(&g_sab[c.x], v0.x, v0.y);
            red_add_v2(&g_sab[c.y], v1.x, v1.y);
            red_add_v2(&g_sab[c.z], v2.x, v2.y);
            red_add_v2(&g_sab[c.w], v3.x, v3.y);
        }
    }
}

// K-node2: reconstruct h1 (64-wide), relu, dot W2 -> q = dinv * p
__global__ void __launch_bounds__(256) k_node2(const float* __restrict__ W1,
                                               const float* __restrict__ b1,
                                               const float* __restrict__ W2, int n) {
    __shared__ float sW10[64], sW11[64], sB1[64], sW2[64];
    int t = threadIdx.x;
    if (t < 64) {
        sW10[t] = W1[t];
        sW11[t] = W1[64 + t];
        sB1[t]  = b1[t];
        sW2[t]  = W2[t];
    }
    __syncthreads();
    int i = blockIdx.x * blockDim.x + t;
    if (i < n) {
        float dinv = g_dinv[i];
        float2 self = g_ab[i];
        float2 acc  = g_sab[i];
        float ca = acc.x + self.x;
        float cb = acc.y + self.y;
        float p = 0.0f;
        #pragma unroll
        for (int j = 0; j < 64; j++) {
            float h = fmaf(dinv, fmaf(ca, sW10[j], cb * sW11[j]), sB1[j]);
            h = fmaxf(h, 0.0f);
            p = fmaf(h, sW2[j], p);
        }
        g_q[i] = dinv * p;
    }
}

// K-scatter2: 8 edges per thread in two sequential int4 groups.
__global__ void __launch_bounds__(256) k_scatter2(const int4* __restrict__ row4,
                                                  const int4* __restrict__ col4) {
    int i = (blockIdx.x * blockDim.x + threadIdx.x) * 2;
    #pragma unroll
    for (int u = 0; u < 2; u++) {
        int idx = i + u;
        if (idx < E4) {
            int4 r = __ldg(&row4[idx]);
            int4 c = __ldg(&col4[idx]);
            float q0 = __ldg(&g_q[r.x]);
            float q1 = __ldg(&g_q[r.y]);
            float q2 = __ldg(&g_q[r.z]);
            float q3 = __ldg(&g_q[r.w]);
            red_add_f(&g_t[c.x], q0);
            red_add_f(&g_t[c.y], q1);
            red_add_f(&g_t[c.z], q2);
            red_add_f(&g_t[c.w], q3);
        }
    }
}

// K-final
__global__ void __launch_bounds__(256) k_final(const float* __restrict__ b2,
                                               float* __restrict__ out, int n) {
    int i = blockIdx.x * blockDim.x + threadIdx.x;
    if (i < n) {
        out[i] = fmaf(g_dinv[i], g_t[i] + g_q[i], b2[0]);
    }
}

extern "C" void kernel_launch(void* const* d_in, const int* in_sizes, int n_in,
                              void* d_out, int out_size) {
    const float* x   = (const float*)d_in[0];
    const int*   ei  = (const int*)d_in[1];
    const float* W1  = (const float*)d_in[2];
    const float* b1  = (const float*)d_in[3];
    const float* W2  = (const float*)d_in[4];
    const float* b2  = (const float*)d_in[5];
    float* out = (float*)d_out;

    const int n = NN;
    const int4* row4 = (const int4*)ei;
    const int4* col4 = (const int4*)(ei + EE);

    const int TB = 256;
    const int gN = (n + TB - 1) / TB;
    const int gE = (E4 / 2 + TB - 1) / TB;   // 2 int4 (8 edges) per thread

    // Zero accumulators via HW memset (graph-capturable, async on stream 0)
    static float*  p_deg = nullptr;
    static float2* p_sab = nullptr;
    static float*  p_t   = nullptr;
    if (!p_deg) {
        cudaGetSymbolAddress((void**)&p_deg, g_deg);
        cudaGetSymbolAddress((void**)&p_sab, g_sab);
        cudaGetSymbolAddress((void**)&p_t,   g_t);
    }
    cudaMemsetAsync(p_deg, 0, NN * sizeof(float));
    cudaMemsetAsync(p_sab, 0, NN * sizeof(float2));
    cudaMemsetAsync(p_t,   0, NN * sizeof(float));

    k_deg     <<<gE, TB>>>(col4);
    k_node1   <<<gN, TB>>>(x, n);
    k_scatter1<<<gE, TB>>>(row4, col4);
    k_node2   <<<gN, TB>>>(W1, b1, W2, n);
    k_scatter2<<<gE, TB>>>(row4, col4);
    k_final   <<<gN, TB>>>(b2, out, n);
}

// round 6
// speedup vs baseline: 1.1571x; 1.0245x over previous
#include <cuda_runtime.h>

#define NN 100000
#define EE 3200000
#define E4 (EE / 4)

// Scratch (__device__ globals; no allocation allowed)
__device__ float  g_deg[NN];
__device__ float  g_dinv[NN];
__device__ float2 g_ab[NN];    // (dinv*x0, dinv*x1) per node
__device__ float2 g_sab[NN];   // layer-1 accumulators
__device__ float  g_q[NN];
__device__ float  g_t[NN];

__device__ __forceinline__ void red_add_v2(float2* addr, float a, float b) {
    asm volatile("red.global.add.v2.f32 [%0], {%1, %2};"
                 :: "l"(addr), "f"(a), "f"(b) : "memory");
}

// K1: init — deg starts at 1 (self-loop). Other accumulators zeroed in k_node1.
__global__ void __launch_bounds__(256) k_init(int n) {
    int i = blockIdx.x * blockDim.x + threadIdx.x;
    if (i < n) {
        g_deg[i] = 1.0f;
    }
}

// K2: degree count over edge destinations (col), int4, 2 per thread
__global__ void __launch_bounds__(256) k_deg(const int4* __restrict__ col4, int e4) {
    int i = (blockIdx.x * blockDim.x + threadIdx.x) * 2;
    #pragma unroll
    for (int u = 0; u < 2; u++) {
        int idx = i + u;
        if (idx < e4) {
            int4 c = __ldg(&col4[idx]);
            atomicAdd(&g_deg[c.x], 1.0f);
            atomicAdd(&g_deg[c.y], 1.0f);
            atomicAdd(&g_deg[c.z], 1.0f);
            atomicAdd(&g_deg[c.w], 1.0f);
        }
    }
}

// K3: per-node dinv + (a,b); also zero the scatter accumulators (runs before
// any scatter kernel touches them).
__global__ void __launch_bounds__(256) k_node1(const float* __restrict__ x, int n) {
    int i = blockIdx.x * blockDim.x + threadIdx.x;
    if (i < n) {
        float dinv = rsqrtf(g_deg[i]);
        float2 xi = ((const float2*)x)[i];
        g_dinv[i] = dinv;
        g_ab[i] = make_float2(dinv * xi.x, dinv * xi.y);
        g_sab[i] = make_float2(0.0f, 0.0f);
        g_t[i] = 0.0f;
    }
}

// K4: layer-1 edge scatter — one 64b gather + one 64b vector red per edge
__global__ void __launch_bounds__(256) k_scatter1(const int4* __restrict__ row4,
                                                  const int4* __restrict__ col4, int e4) {
    int i = (blockIdx.x * blockDim.x + threadIdx.x) * 2;
    #pragma unroll
    for (int u = 0; u < 2; u++) {
        int idx = i + u;
        if (idx < e4) {
            int4 r = __ldg(&row4[idx]);
            int4 c = __ldg(&col4[idx]);
            float2 v0 = __ldg(&g_ab[r.x]);
            float2 v1 = __ldg(&g_ab[r.y]);
            float2 v2 = __ldg(&g_ab[r.z]);
            float2 v3 = __ldg(&g_ab[r.w]);
            red_add_v2(&g_sab[c.x], v0.x, v0.y);
            red_add_v2(&g_sab[c.y], v1.x, v1.y);
            red_add_v2(&g_sab[c.z], v2.x, v2.y);
            red_add_v2(&g_sab[c.w], v3.x, v3.y);
        }
    }
}

// K5: per-node — reconstruct h1 (64-wide), relu, dot W2 -> q = dinv * p
// Two nodes per thread for ILP (two independent fma chains).
__global__ void __launch_bounds__(256) k_node2(const float* __restrict__ W1,
                                               const float* __restrict__ b1,
                                               const float* __restrict__ W2, int n) {
    __shared__ float sW10[64], sW11[64], sB1[64], sW2[64];
    int t = threadIdx.x;
    if (t < 64) {
        sW10[t] = W1[t];
        sW11[t] = W1[64 + t];
        sB1[t]  = b1[t];
        sW2[t]  = W2[t];
    }
    __syncthreads();
    int i0 = blockIdx.x * (blockDim.x * 2) + t;
    int i1 = i0 + blockDim.x;

    float dinv0 = 0.f, ca0 = 0.f, cb0 = 0.f;
    float dinv1 = 0.f, ca1 = 0.f, cb1 = 0.f;
    if (i0 < n) {
        dinv0 = g_dinv[i0];
        float2 s = g_ab[i0], a = g_sab[i0];
        ca0 = a.x + s.x; cb0 = a.y + s.y;
    }
    if (i1 < n) {
        dinv1 = g_dinv[i1];
        float2 s = g_ab[i1], a = g_sab[i1];
        ca1 = a.x + s.x; cb1 = a.y + s.y;
    }
    float p0 = 0.0f, p1 = 0.0f;
    #pragma unroll
    for (int j = 0; j < 64; j++) {
        float w0 = sW10[j], w1 = sW11[j], bb = sB1[j], w2 = sW2[j];
        float h0 = fmaf(dinv0, fmaf(ca0, w0, cb0 * w1), bb);
        float h1 = fmaf(dinv1, fmaf(ca1, w0, cb1 * w1), bb);
        h0 = fmaxf(h0, 0.0f);
        h1 = fmaxf(h1, 0.0f);
        p0 = fmaf(h0, w2, p0);
        p1 = fmaf(h1, w2, p1);
    }
    if (i0 < n) g_q[i0] = dinv0 * p0;
    if (i1 < n) g_q[i1] = dinv1 * p1;
}

// K6: layer-2 edge scatter — one 32b gather + one 32b red per edge
__global__ void __launch_bounds__(256) k_scatter2(const int4* __restrict__ row4,
                                                  const int4* __restrict__ col4, int e4) {
    int i = (blockIdx.x * blockDim.x + threadIdx.x) * 2;
    #pragma unroll
    for (int u = 0; u < 2; u++) {
        int idx = i + u;
        if (idx < e4) {
            int4 r = __ldg(&row4[idx]);
            int4 c = __ldg(&col4[idx]);
            float q0 = __ldg(&g_q[r.x]);
            float q1 = __ldg(&g_q[r.y]);
            float q2 = __ldg(&g_q[r.z]);
            float q3 = __ldg(&g_q[r.w]);
            atomicAdd(&g_t[c.x], q0);
            atomicAdd(&g_t[c.y], q1);
            atomicAdd(&g_t[c.z], q2);
            atomicAdd(&g_t[c.w], q3);
        }
    }
}

// K7: final
__global__ void __launch_bounds__(256) k_final(const float* __restrict__ b2,
                                               float* __restrict__ out, int n) {
    int i = blockIdx.x * blockDim.x + threadIdx.x;
    if (i < n) {
        out[i] = fmaf(g_dinv[i], g_t[i] + g_q[i], b2[0]);
    }
}

extern "C" void kernel_launch(void* const* d_in, const int* in_sizes, int n_in,
                              void* d_out, int out_size) {
    const float* x   = (const float*)d_in[0];
    const int*   ei  = (const int*)d_in[1];
    const float* W1  = (const float*)d_in[2];
    const float* b1  = (const float*)d_in[3];
    const float* W2  = (const float*)d_in[4];
    const float* b2  = (const float*)d_in[5];
    float* out = (float*)d_out;

    const int n = NN;
    const int e4 = E4;
    const int4* row4 = (const int4*)ei;
    const int4* col4 = (const int4*)(ei + EE);

    const int TB = 256;
    const int gN  = (n + TB - 1) / TB;
    const int gN2 = (n + TB * 2 - 1) / (TB * 2);
    const int gE2 = (e4 / 2 + TB - 1) / TB;   // 2 int4 per thread

    k_init    <<<gN, TB>>>(n);
    k_deg     <<<gE2, TB>>>(col4, e4);
    k_node1   <<<gN, TB>>>(x, n);
    k_scatter1<<<gE2, TB>>>(row4, col4, e4);
    k_node2   <<<gN2, TB>>>(W1, b1, W2, n);
    k_scatter2<<<gE2, TB>>>(row4, col4, e4);
    k_final   <<<gN, TB>>>(b2, out, n);
}

// round 9
// speedup vs baseline: 1.2761x; 1.1028x over previous
#include <cuda_runtime.h>

#define NN 100000
#define EE 3200000
#define E4 (EE / 4)

// Scratch (__device__ globals; zero-initialized at module load).
// INVARIANT: g_deg, g_sab, g_t are zero at entry to kernel_launch; k_final
// re-zeroes them after use so the invariant holds for the next call.
__device__ float  g_deg[NN];
__device__ float  g_dinv[NN];
__device__ float2 g_ab[NN];    // (dinv*x0, dinv*x1) per node
__device__ float2 g_sab[NN];   // layer-1 accumulators
__device__ float  g_q[NN];
__device__ float  g_t[NN];

__device__ __forceinline__ void red_add_v2(float2* addr, float a, float b) {
    asm volatile("red.global.add.v2.f32 [%0], {%1, %2};"
                 :: "l"(addr), "f"(a), "f"(b) : "memory");
}

// K1: degree count over edge destinations (col), int4, 2 per thread
__global__ void __launch_bounds__(256) k_deg(const int4* __restrict__ col4, int e4) {
    int i = (blockIdx.x * blockDim.x + threadIdx.x) * 2;
    #pragma unroll
    for (int u = 0; u < 2; u++) {
        int idx = i + u;
        if (idx < e4) {
            int4 c = __ldg(&col4[idx]);
            atomicAdd(&g_deg[c.x], 1.0f);
            atomicAdd(&g_deg[c.y], 1.0f);
            atomicAdd(&g_deg[c.z], 1.0f);
            atomicAdd(&g_deg[c.w], 1.0f);
        }
    }
}

// K2: per-node dinv = rsqrt(deg + 1 self-loop); (a,b) = dinv * x
__global__ void __launch_bounds__(256) k_node1(const float* __restrict__ x, int n) {
    int i = blockIdx.x * blockDim.x + threadIdx.x;
    if (i < n) {
        float dinv = rsqrtf(g_deg[i] + 1.0f);
        float2 xi = ((const float2*)x)[i];
        g_dinv[i] = dinv;
        g_ab[i] = make_float2(dinv * xi.x, dinv * xi.y);
    }
}

// K3: layer-1 edge scatter — one 64b gather + one 64b vector RED per edge
__global__ void __launch_bounds__(256) k_scatter1(const int4* __restrict__ row4,
                                                  const int4* __restrict__ col4, int e4) {
    int i = (blockIdx.x * blockDim.x + threadIdx.x) * 2;
    #pragma unroll
    for (int u = 0; u < 2; u++) {
        int idx = i + u;
        if (idx < e4) {
            int4 r = __ldg(&row4[idx]);
            int4 c = __ldg(&col4[idx]);
            float2 v0 = __ldg(&g_ab[r.x]);
            float2 v1 = __ldg(&g_ab[r.y]);
            float2 v2 = __ldg(&g_ab[r.z]);
            float2 v3 = __ldg(&g_ab[r.w]);
            red_add_v2(&g_sab[c.x], v0.x, v0.y);
            red_add_v2(&g_sab[c.y], v1.x, v1.y);
            red_add_v2(&g_sab[c.z], v2.x, v2.y);
            red_add_v2(&g_sab[c.w], v3.x, v3.y);
        }
    }
}

// K4: per-node MLP — reconstruct h1 (64-wide), relu, dot W2 -> q = dinv * p
// Two nodes per thread for ILP.
__global__ void __launch_bounds__(256) k_node2(const float* __restrict__ W1,
                                               const float* __restrict__ b1,
                                               const float* __restrict__ W2, int n) {
    __shared__ float sW10[64], sW11[64], sB1[64], sW2[64];
    int t = threadIdx.x;
    if (t < 64) {
        sW10[t] = W1[t];
        sW11[t] = W1[64 + t];
        sB1[t]  = b1[t];
        sW2[t]  = W2[t];
    }
    __syncthreads();
    int i0 = blockIdx.x * (blockDim.x * 2) + t;
    int i1 = i0 + blockDim.x;

    float dinv0 = 0.f, ca0 = 0.f, cb0 = 0.f;
    float dinv1 = 0.f, ca1 = 0.f, cb1 = 0.f;
    if (i0 < n) {
        dinv0 = g_dinv[i0];
        float2 s = g_ab[i0], a = g_sab[i0];
        ca0 = a.x + s.x; cb0 = a.y + s.y;
    }
    if (i1 < n) {
        dinv1 = g_dinv[i1];
        float2 s = g_ab[i1], a = g_sab[i1];
        ca1 = a.x + s.x; cb1 = a.y + s.y;
    }
    float p0 = 0.0f, p1 = 0.0f;
    #pragma unroll
    for (int j = 0; j < 64; j++) {
        float w0 = sW10[j], w1 = sW11[j], bb = sB1[j], w2 = sW2[j];
        float h0 = fmaf(dinv0, fmaf(ca0, w0, cb0 * w1), bb);
        float h1 = fmaf(dinv1, fmaf(ca1, w0, cb1 * w1), bb);
        h0 = fmaxf(h0, 0.0f);
        h1 = fmaxf(h1, 0.0f);
        p0 = fmaf(h0, w2, p0);
        p1 = fmaf(h1, w2, p1);
    }
    if (i0 < n) g_q[i0] = dinv0 * p0;
    if (i1 < n) g_q[i1] = dinv1 * p1;
}

// K5: layer-2 edge scatter — one 32b gather + one 32b RED per edge
__global__ void __launch_bounds__(256) k_scatter2(const int4* __restrict__ row4,
                                                  const int4* __restrict__ col4, int e4) {
    int i = (blockIdx.x * blockDim.x + threadIdx.x) * 2;
    #pragma unroll
    for (int u = 0; u < 2; u++) {
        int idx = i + u;
        if (idx < e4) {
            int4 r = __ldg(&row4[idx]);
            int4 c = __ldg(&col4[idx]);
            float q0 = __ldg(&g_q[r.x]);
            float q1 = __ldg(&g_q[r.y]);
            float q2 = __ldg(&g_q[r.z]);
            float q3 = __ldg(&g_q[r.w]);
            atomicAdd(&g_t[c.x], q0);
            atomicAdd(&g_t[c.y], q1);
            atomicAdd(&g_t[c.z], q2);
            atomicAdd(&g_t[c.w], q3);
        }
    }
}

// K6: final — emit output AND restore the zero-scratch invariant.
__global__ void __launch_bounds__(256) k_final(const float* __restrict__ b2,
                                               float* __restrict__ out, int n) {
    int i = blockIdx.x * blockDim.x + threadIdx.x;
    if (i < n) {
        out[i] = fmaf(g_dinv[i], g_t[i] + g_q[i], b2[0]);
        g_deg[i] = 0.0f;
        g_sab[i] = make_float2(0.0f, 0.0f);
        g_t[i]   = 0.0f;
    }
}

extern "C" void kernel_launch(void* const* d_in, const int* in_sizes, int n_in,
                              void* d_out, int out_size) {
    const float* x   = (const float*)d_in[0];
    const int*   ei  = (const int*)d_in[1];
    const float* W1  = (const float*)d_in[2];
    const float* b1  = (const float*)d_in[3];
    const float* W2  = (const float*)d_in[4];
    const float* b2  = (const float*)d_in[5];
    float* out = (float*)d_out;

    const int n = NN;
    const int e4 = E4;
    const int4* row4 = (const int4*)ei;
    const int4* col4 = (const int4*)(ei + EE);

    const int TB = 256;
    const int gN  = (n + TB - 1) / TB;
    const int gN2 = (n + TB * 2 - 1) / (TB * 2);
    const int gE2 = (e4 / 2 + TB - 1) / TB;   // 2 int4 per thread

    k_deg     <<<gE2, TB>>>(col4, e4);
    k_node1   <<<gN, TB>>>(x, n);
    k_scatter1<<<gE2, TB>>>(row4, col4, e4);
    k_node2   <<<gN2, TB>>>(W1, b1, W2, n);
    k_scatter2<<<gE2, TB>>>(row4, col4, e4);
    k_final   <<<gN, TB>>>(b2, out, n);
}